// round 15
// baseline (speedup 1.0000x reference)
#include <cuda_runtime.h>

// Problem constants (from reference)
#define NPTS   4096
#define BATCH  (1 << 20)
#define NNODE  4096
#define PLANE  (NNODE * NNODE)        // 16777216
#define TAU_MAX 10.0f

#define NBINS  4096
#define BUILD_THREADS (8 * (NPTS + 1))        // 32776
#define BUILD_BLOCKS  ((BUILD_THREADS + 255) / 256)   // 129
#define HIST_BLOCKS   (BATCH / 256)           // 4096

// LUTs: f_i over dt/100 in [-1, 0.1], g_i over ty/100 in [0,1]. float4 per point.
__device__ __align__(16) float g_tabX[(NPTS + 1) * 4];
__device__ __align__(16) float g_tabY[(NPTS + 1) * 4];

// Sort scratch. g_hist is zero at process start and re-zeroed by scan_kernel
// each invocation -> deterministic across graph replays.
__device__ int g_hist[NBINS];
__device__ int g_cursor[NBINS];
__device__ __align__(16) float4 g_sorted[BATCH];   // (tx, ty, pack(yi,xi), orig)

// softplus(100 z)/100, numerically stable.
__device__ __forceinline__ float sp100(float z) {
    float u = 100.0f * z;
    float r = fmaxf(u, 0.0f);
    float e = __expf(-fabsf(u));
    return (r + __logf(1.0f + e)) * 0.01f;
}

// K1: fused LUT build (blocks [0, BUILD_BLOCKS)) + yi histogram (rest).
__global__ void build_hist_kernel(
    const float2* __restrict__ y,
    const float* __restrict__ Wx1, const float* __restrict__ Wx2, const float* __restrict__ Wx3,
    const float* __restrict__ Wy1, const float* __restrict__ Wy2, const float* __restrict__ Wy3,
    const float* __restrict__ bx1, const float* __restrict__ bx2, const float* __restrict__ bx3,
    const float* __restrict__ by1, const float* __restrict__ by2, const float* __restrict__ by3)
{
    if (blockIdx.x < BUILD_BLOCKS) {
        int tid = blockIdx.x * 256 + threadIdx.x;
        if (tid >= BUILD_THREADS) return;
        int  i   = tid % (NPTS + 1);
        int  rem = tid / (NPTS + 1);       // 0..7
        int  n   = rem & 3;
        bool isY = (rem >> 2) != 0;

        float t = isY ? (float)i * (1.0f / NPTS)
                      : (-1.0f + (float)i * (1.1f / NPTS));

        const float* W1 = isY ? Wy1 : Wx1;
        const float* W2 = isY ? Wy2 : Wx2;
        const float* W3 = isY ? Wy3 : Wx3;
        const float* b1 = isY ? by1 : bx1;
        const float* b2 = isY ? by2 : bx2;
        const float* b3 = isY ? by3 : bx3;

        float h1[5];
#pragma unroll
        for (int w = 0; w < 5; w++)
            h1[w] = sp100(fmaf(t, __ldg(&W1[n * 5 + w]), __ldg(&b1[n * 5 + w])));
        float h2[5];
#pragma unroll
        for (int v = 0; v < 5; v++) {
            float z = __ldg(&b2[n * 5 + v]);
#pragma unroll
            for (int w = 0; w < 5; w++)
                z = fmaf(h1[w], __ldg(&W2[n * 25 + w * 5 + v]), z);
            h2[v] = sp100(z);
        }
        float z = __ldg(&b3[n]);
#pragma unroll
        for (int w = 0; w < 5; w++)
            z = fmaf(h2[w], __ldg(&W3[n * 5 + w]), z);

        float* tab = isY ? g_tabY : g_tabX;
        tab[i * 4 + n] = z;
    } else {
        int s = (blockIdx.x - BUILD_BLOCKS) * 256 + threadIdx.x;   // < BATCH exactly
        float2 yv = __ldcs(&y[s]);
        int yi = (int)yv.y;
        atomicAdd(&g_hist[yi], 1);
    }
}

// K2: single-block exclusive scan of g_hist -> g_cursor; re-zero g_hist.
__global__ void __launch_bounds__(1024) scan_kernel()
{
    __shared__ int warp_sums[32];
    int t = threadIdx.x;                  // 0..1023, 4 bins each
    int v0 = g_hist[4 * t];
    int v1 = g_hist[4 * t + 1];
    int v2 = g_hist[4 * t + 2];
    int v3 = g_hist[4 * t + 3];
    int s = v0 + v1 + v2 + v3;

    int lane = t & 31, wid = t >> 5;
    int inc = s;
#pragma unroll
    for (int d = 1; d < 32; d <<= 1) {
        int nv = __shfl_up_sync(0xFFFFFFFFu, inc, d);
        if (lane >= d) inc += nv;
    }
    if (lane == 31) warp_sums[wid] = inc;
    __syncthreads();
    if (wid == 0) {
        int ws = warp_sums[lane];
#pragma unroll
        for (int d = 1; d < 32; d <<= 1) {
            int nv = __shfl_up_sync(0xFFFFFFFFu, ws, d);
            if (lane >= d) ws += nv;
        }
        warp_sums[lane] = ws;
    }
    __syncthreads();
    int base = inc - s + (wid > 0 ? warp_sums[wid - 1] : 0);   // exclusive prefix

    g_cursor[4 * t]     = base;
    g_cursor[4 * t + 1] = base + v0;
    g_cursor[4 * t + 2] = base + v0 + v1;
    g_cursor[4 * t + 3] = base + v0 + v1 + v2;
    // reset for next invocation (determinism across graph replays)
    g_hist[4 * t] = 0; g_hist[4 * t + 1] = 0; g_hist[4 * t + 2] = 0; g_hist[4 * t + 3] = 0;
}

// K3: scatter samples into yi-sorted order.
__global__ void __launch_bounds__(256)
scatter_kernel(const float2* __restrict__ x, const float2* __restrict__ y)
{
    int i = blockIdx.x * 256 + threadIdx.x;
    float2 xv = __ldcs(&x[i]);
    float2 yv = __ldcs(&y[i]);
    int xi = (int)xv.y;
    int yi = (int)yv.y;
    int pos = atomicAdd(&g_cursor[yi], 1);
    unsigned pk = ((unsigned)yi << 12) | (unsigned)xi;
    g_sorted[pos] = make_float4(xv.x, yv.x, __int_as_float((int)pk), __int_as_float(i));
}

// K4: eval in sorted order. Consecutive threads share yi -> B-row locality.
__global__ void __launch_bounds__(256)
eval_kernel(const float* __restrict__ B, const float* __restrict__ W,
            float* __restrict__ out)
{
    int b = blockIdx.x * 256 + threadIdx.x;
    float4 s = g_sorted[b];                 // coalesced 16B
    float tx = s.x, ty = s.y;
    unsigned pk = __float_as_uint(s.z);
    int xi = (int)(pk & 4095u);
    int yi = (int)((pk >> 12) & 4095u);
    int orig = __float_as_int(s.w);

    float dt = tx - ty;
    bool  m  = (dt <= TAU_MAX);

    // Clustered gathers (same B row across the warp) -> L1/L2 hits, row-buffer friendly.
    const float* Bp = B + (yi * NNODE + xi);
    float v0 = m ? Bp[0]         : 0.0f;
    float v1 = m ? Bp[PLANE]     : 0.0f;
    float v2 = m ? Bp[2 * PLANE] : 0.0f;
    float v3 = m ? Bp[3 * PLANE] : 0.0f;

    const float4* W4 = (const float4*)W;
    float4 w0 = __ldg(&W4[0]);
    float4 w1 = __ldg(&W4[1]);
    float4 w2 = __ldg(&W4[2]);
    float4 w3 = __ldg(&W4[3]);

    float px = fmaf(dt, 0.01f, 1.0f) * ((float)NPTS / 1.1f);
    px = fminf(fmaxf(px, 0.0f), (float)NPTS);
    int   ix = min((int)px, NPTS - 1);
    float fx = px - (float)ix;

    float py = ty * (0.01f * (float)NPTS);
    py = fminf(fmaxf(py, 0.0f), (float)NPTS);
    int   iy = min((int)py, NPTS - 1);
    float fy = py - (float)iy;

    const float4* tX = (const float4*)g_tabX;
    const float4* tY = (const float4*)g_tabY;
    float4 a0 = __ldg(&tX[ix]);
    float4 a1 = __ldg(&tX[ix + 1]);
    float4 c0 = __ldg(&tY[iy]);
    float4 c1 = __ldg(&tY[iy + 1]);

    float k0 = fmaf(fx, a1.x - a0.x, a0.x) * fmaf(fy, c1.x - c0.x, c0.x);
    float k1 = fmaf(fx, a1.y - a0.y, a0.y) * fmaf(fy, c1.y - c0.y, c0.y);
    float k2 = fmaf(fx, a1.z - a0.z, a0.z) * fmaf(fy, c1.z - c0.z, c0.z);
    float k3 = fmaf(fx, a1.w - a0.w, a0.w) * fmaf(fy, c1.w - c0.w, c0.w);

    float cj0 = fmaf(k3, w3.x, fmaf(k2, w2.x, fmaf(k1, w1.x, k0 * w0.x)));
    float cj1 = fmaf(k3, w3.y, fmaf(k2, w2.y, fmaf(k1, w1.y, k0 * w0.y)));
    float cj2 = fmaf(k3, w3.z, fmaf(k2, w2.z, fmaf(k1, w1.z, k0 * w0.z)));
    float cj3 = fmaf(k3, w3.w, fmaf(k2, w2.w, fmaf(k1, w1.w, k0 * w0.w)));

    float res = fmaf(cj3, v3, fmaf(cj2, v2, fmaf(cj1, v1, cj0 * v0)));
    // Scattered 4B store; out (4MB) lives in L2 and merges to full sectors.
    out[orig] = m ? res : 0.0f;
}

extern "C" void kernel_launch(void* const* d_in, const int* in_sizes, int n_in,
                              void* d_out, int out_size)
{
    const float* x   = (const float*)d_in[0];
    const float* y   = (const float*)d_in[1];
    const float* B   = (const float*)d_in[2];
    const float* Wx1 = (const float*)d_in[3];
    const float* Wx2 = (const float*)d_in[4];
    const float* Wx3 = (const float*)d_in[5];
    const float* Wy1 = (const float*)d_in[6];
    const float* Wy2 = (const float*)d_in[7];
    const float* Wy3 = (const float*)d_in[8];
    const float* bx1 = (const float*)d_in[9];
    const float* bx2 = (const float*)d_in[10];
    const float* bx3 = (const float*)d_in[11];
    const float* by1 = (const float*)d_in[12];
    const float* by2 = (const float*)d_in[13];
    const float* by3 = (const float*)d_in[14];
    const float* W   = (const float*)d_in[15];

    // K1: LUT build + yi histogram (fused).
    build_hist_kernel<<<BUILD_BLOCKS + HIST_BLOCKS, 256>>>(
        (const float2*)y,
        Wx1, Wx2, Wx3, Wy1, Wy2, Wy3, bx1, bx2, bx3, by1, by2, by3);

    // K2: scan + hist reset.
    scan_kernel<<<1, 1024>>>();

    // K3: scatter into sorted order.
    scatter_kernel<<<BATCH / 256, 256>>>((const float2*)x, (const float2*)y);

    // K4: eval.
    eval_kernel<<<BATCH / 256, 256>>>(B, W, (float*)d_out);
}

// round 17
// speedup vs baseline: 1.8907x; 1.8907x over previous
#include <cuda_runtime.h>

// Problem constants (from reference)
#define NPTS   4096
#define BATCH  (1 << 20)
#define NNODE  4096
#define PLANE  (NNODE * NNODE)        // 16777216
#define TAU_MAX 10.0f

#define NBINS  4096
#define BUILD_THREADS (8 * (NPTS + 1))              // 32776
#define LUT_BLOCKS    ((BUILD_THREADS + 1023) / 1024)   // 33
#define SORT_BLOCKS   128
#define WINDOW        (BATCH / SORT_BLOCKS)         // 8192 samples per block

// LUTs: f_i over dt/100 in [-1, 0.1], g_i over ty/100 in [0,1]. float4 per point.
__device__ __align__(16) float g_tabX[(NPTS + 1) * 4];
__device__ __align__(16) float g_tabY[(NPTS + 1) * 4];

// Sort state. g_hist zero at load; scan re-zeroes it each replay (determinism).
// g_cursor rewritten by scan each replay before scatter mutates it.
__device__ int g_hist[NBINS];
__device__ int g_cursor[NBINS];
__device__ int g_total;
__device__ __align__(16) float4 g_sorted[BATCH];   // (tx, ty, pack(yi,xi), orig) -- masked-in only

// softplus(100 z)/100, numerically stable.
__device__ __forceinline__ float sp100(float z) {
    float u = 100.0f * z;
    float r = fmaxf(u, 0.0f);
    float e = __expf(-fabsf(u));
    return (r + __logf(1.0f + e)) * 0.01f;
}

// K1: fused. Blocks [0, LUT_BLOCKS): build LUTs. Blocks [LUT_BLOCKS, +SORT_BLOCKS):
// privatized yi-histogram of MASKED samples (smem counts, one spread global add
// per nonzero bin -- no contended atomics). Also warms x/y into L2 for K3.
__global__ void __launch_bounds__(1024) build_hist_kernel(
    const float2* __restrict__ x, const float2* __restrict__ y,
    const float* __restrict__ Wx1, const float* __restrict__ Wx2, const float* __restrict__ Wx3,
    const float* __restrict__ Wy1, const float* __restrict__ Wy2, const float* __restrict__ Wy3,
    const float* __restrict__ bx1, const float* __restrict__ bx2, const float* __restrict__ bx3,
    const float* __restrict__ by1, const float* __restrict__ by2, const float* __restrict__ by3)
{
    if (blockIdx.x < LUT_BLOCKS) {
        int tid = blockIdx.x * 1024 + threadIdx.x;
        if (tid >= BUILD_THREADS) return;
        int  i   = tid % (NPTS + 1);
        int  rem = tid / (NPTS + 1);       // 0..7
        int  n   = rem & 3;
        bool isY = (rem >> 2) != 0;

        float t = isY ? (float)i * (1.0f / NPTS)
                      : (-1.0f + (float)i * (1.1f / NPTS));

        const float* W1 = isY ? Wy1 : Wx1;
        const float* W2 = isY ? Wy2 : Wx2;
        const float* W3 = isY ? Wy3 : Wx3;
        const float* b1 = isY ? by1 : bx1;
        const float* b2 = isY ? by2 : bx2;
        const float* b3 = isY ? by3 : bx3;

        float h1[5];
#pragma unroll
        for (int w = 0; w < 5; w++)
            h1[w] = sp100(fmaf(t, __ldg(&W1[n * 5 + w]), __ldg(&b1[n * 5 + w])));
        float h2[5];
#pragma unroll
        for (int v = 0; v < 5; v++) {
            float z = __ldg(&b2[n * 5 + v]);
#pragma unroll
            for (int w = 0; w < 5; w++)
                z = fmaf(h1[w], __ldg(&W2[n * 25 + w * 5 + v]), z);
            h2[v] = sp100(z);
        }
        float z = __ldg(&b3[n]);
#pragma unroll
        for (int w = 0; w < 5; w++)
            z = fmaf(h2[w], __ldg(&W3[n * 5 + w]), z);

        float* tab = isY ? g_tabY : g_tabX;
        tab[i * 4 + n] = z;
    } else {
        __shared__ int s_bin[NBINS];
        int tid = threadIdx.x;
        for (int j = tid; j < NBINS; j += 1024) s_bin[j] = 0;
        __syncthreads();

        int base = (blockIdx.x - LUT_BLOCKS) * WINDOW;
#pragma unroll
        for (int it = 0; it < WINDOW / 1024; it++) {
            int i = base + it * 1024 + tid;
            float2 xv = x[i];
            float2 yv = y[i];
            if (xv.x - yv.x <= TAU_MAX)
                atomicAdd(&s_bin[(int)yv.y], 1);
        }
        __syncthreads();
        for (int j = tid; j < NBINS; j += 1024) {
            int c = s_bin[j];
            if (c) atomicAdd(&g_hist[j], c);   // spread addresses, no return: REDG path
        }
    }
}

// K2: single-block exclusive scan of g_hist -> g_cursor (bin starts); total; re-zero hist.
__global__ void __launch_bounds__(1024) scan_kernel()
{
    __shared__ int warp_sums[32];
    int t = threadIdx.x;                  // 0..1023, 4 bins each
    int v0 = g_hist[4 * t];
    int v1 = g_hist[4 * t + 1];
    int v2 = g_hist[4 * t + 2];
    int v3 = g_hist[4 * t + 3];
    int s = v0 + v1 + v2 + v3;

    int lane = t & 31, wid = t >> 5;
    int inc = s;
#pragma unroll
    for (int d = 1; d < 32; d <<= 1) {
        int nv = __shfl_up_sync(0xFFFFFFFFu, inc, d);
        if (lane >= d) inc += nv;
    }
    if (lane == 31) warp_sums[wid] = inc;
    __syncthreads();
    if (wid == 0) {
        int ws = warp_sums[lane];
#pragma unroll
        for (int d = 1; d < 32; d <<= 1) {
            int nv = __shfl_up_sync(0xFFFFFFFFu, ws, d);
            if (lane >= d) ws += nv;
        }
        warp_sums[lane] = ws;
    }
    __syncthreads();
    int base = inc - s + (wid > 0 ? warp_sums[wid - 1] : 0);   // exclusive prefix

    g_cursor[4 * t]     = base;
    g_cursor[4 * t + 1] = base + v0;
    g_cursor[4 * t + 2] = base + v0 + v1;
    g_cursor[4 * t + 3] = base + v0 + v1 + v2;
    if (t == 1023) g_total = base + s;
    // reset for next replay (determinism)
    g_hist[4 * t] = 0; g_hist[4 * t + 1] = 0; g_hist[4 * t + 2] = 0; g_hist[4 * t + 3] = 0;
}

// K3: privatized scatter. Pass1: smem count (x/y from L2/L1 -- warmed by K1).
// Reserve: one spread global atomicAdd per nonzero bin -> block base, stored in smem.
// Pass2: re-read (L1/L2-hot window), smem-cursor position, write record / zero out.
__global__ void __launch_bounds__(1024)
scatter_kernel(const float2* __restrict__ x, const float2* __restrict__ y,
               float* __restrict__ out)
{
    __shared__ int s_bin[NBINS];
    int tid = threadIdx.x;
    for (int j = tid; j < NBINS; j += 1024) s_bin[j] = 0;
    __syncthreads();

    int base = blockIdx.x * WINDOW;
#pragma unroll
    for (int it = 0; it < WINDOW / 1024; it++) {
        int i = base + it * 1024 + tid;
        float2 xv = x[i];
        float2 yv = y[i];
        if (xv.x - yv.x <= TAU_MAX)
            atomicAdd(&s_bin[(int)yv.y], 1);
    }
    __syncthreads();
    // Reserve global ranges; overwrite count with this block's global write cursor.
    for (int j = tid; j < NBINS; j += 1024) {
        int c = s_bin[j];
        s_bin[j] = c ? atomicAdd(&g_cursor[j], c) : 0;
    }
    __syncthreads();
#pragma unroll
    for (int it = 0; it < WINDOW / 1024; it++) {
        int i = base + it * 1024 + tid;
        float2 xv = x[i];
        float2 yv = y[i];
        if (xv.x - yv.x <= TAU_MAX) {
            int yi = (int)yv.y;
            int xi = (int)xv.y;
            int pos = atomicAdd(&s_bin[yi], 1);
            unsigned pk = ((unsigned)yi << 12) | (unsigned)xi;
            g_sorted[pos] = make_float4(xv.x, yv.x,
                                        __int_as_float((int)pk), __int_as_float(i));
        } else {
            out[i] = 0.0f;   // masked-out: output is zero, not evaluated
        }
    }
}

// K4: eval over the compacted, yi-sorted stream (all records masked-in).
__global__ void __launch_bounds__(256)
eval_kernel(const float* __restrict__ B, const float* __restrict__ W,
            float* __restrict__ out)
{
    int b = blockIdx.x * 256 + threadIdx.x;
    if (b >= g_total) return;

    float4 s = __ldcs(&g_sorted[b]);        // coalesced 16B, single-use
    float tx = s.x, ty = s.y;
    unsigned pk = __float_as_uint(s.z);
    int xi = (int)(pk & 4095u);
    int yi = (int)((pk >> 12) & 4095u);
    int orig = __float_as_int(s.w);

    // Clustered gathers: consecutive threads share yi -> B-row locality in L1/L2.
    const float* Bp = B + (yi * NNODE + xi);
    float v0 = Bp[0];
    float v1 = Bp[PLANE];
    float v2 = Bp[2 * PLANE];
    float v3 = Bp[3 * PLANE];

    const float4* W4 = (const float4*)W;
    float4 w0 = __ldg(&W4[0]);
    float4 w1 = __ldg(&W4[1]);
    float4 w2 = __ldg(&W4[2]);
    float4 w3 = __ldg(&W4[3]);

    float dt = tx - ty;
    float px = fmaf(dt, 0.01f, 1.0f) * ((float)NPTS / 1.1f);
    px = fminf(fmaxf(px, 0.0f), (float)NPTS);
    int   ix = min((int)px, NPTS - 1);
    float fx = px - (float)ix;

    float py = ty * (0.01f * (float)NPTS);
    py = fminf(fmaxf(py, 0.0f), (float)NPTS);
    int   iy = min((int)py, NPTS - 1);
    float fy = py - (float)iy;

    const float4* tX = (const float4*)g_tabX;
    const float4* tY = (const float4*)g_tabY;
    float4 a0 = __ldg(&tX[ix]);
    float4 a1 = __ldg(&tX[ix + 1]);
    float4 c0 = __ldg(&tY[iy]);
    float4 c1 = __ldg(&tY[iy + 1]);

    float k0 = fmaf(fx, a1.x - a0.x, a0.x) * fmaf(fy, c1.x - c0.x, c0.x);
    float k1 = fmaf(fx, a1.y - a0.y, a0.y) * fmaf(fy, c1.y - c0.y, c0.y);
    float k2 = fmaf(fx, a1.z - a0.z, a0.z) * fmaf(fy, c1.z - c0.z, c0.z);
    float k3 = fmaf(fx, a1.w - a0.w, a0.w) * fmaf(fy, c1.w - c0.w, c0.w);

    float cj0 = fmaf(k3, w3.x, fmaf(k2, w2.x, fmaf(k1, w1.x, k0 * w0.x)));
    float cj1 = fmaf(k3, w3.y, fmaf(k2, w2.y, fmaf(k1, w1.y, k0 * w0.y)));
    float cj2 = fmaf(k3, w3.z, fmaf(k2, w2.z, fmaf(k1, w1.z, k0 * w0.z)));
    float cj3 = fmaf(k3, w3.w, fmaf(k2, w2.w, fmaf(k1, w1.w, k0 * w0.w)));

    out[orig] = fmaf(cj3, v3, fmaf(cj2, v2, fmaf(cj1, v1, cj0 * v0)));
}

extern "C" void kernel_launch(void* const* d_in, const int* in_sizes, int n_in,
                              void* d_out, int out_size)
{
    const float* x   = (const float*)d_in[0];
    const float* y   = (const float*)d_in[1];
    const float* B   = (const float*)d_in[2];
    const float* Wx1 = (const float*)d_in[3];
    const float* Wx2 = (const float*)d_in[4];
    const float* Wx3 = (const float*)d_in[5];
    const float* Wy1 = (const float*)d_in[6];
    const float* Wy2 = (const float*)d_in[7];
    const float* Wy3 = (const float*)d_in[8];
    const float* bx1 = (const float*)d_in[9];
    const float* bx2 = (const float*)d_in[10];
    const float* bx3 = (const float*)d_in[11];
    const float* by1 = (const float*)d_in[12];
    const float* by2 = (const float*)d_in[13];
    const float* by3 = (const float*)d_in[14];
    const float* W   = (const float*)d_in[15];

    // K1: LUT build + privatized masked-yi histogram (warms x/y into L2).
    build_hist_kernel<<<LUT_BLOCKS + SORT_BLOCKS, 1024>>>(
        (const float2*)x, (const float2*)y,
        Wx1, Wx2, Wx3, Wy1, Wy2, Wy3, bx1, bx2, bx3, by1, by2, by3);

    // K2: scan -> bin starts + total; reset hist for replay determinism.
    scan_kernel<<<1, 1024>>>();

    // K3: privatized scatter into sorted compact stream; zero-fill masked-out outputs.
    scatter_kernel<<<SORT_BLOCKS, 1024>>>(
        (const float2*)x, (const float2*)y, (float*)d_out);

    // K4: eval.
    eval_kernel<<<BATCH / 256, 256>>>(B, W, (float*)d_out);
}